// round 3
// baseline (speedup 1.0000x reference)
#include <cuda_runtime.h>
#include <math.h>

// Problem constants
#define NB     8
#define D_IN   514
#define T_IN   4000
#define NCOLS  (NB * T_IN)     // 32000 columns (b,t)
#define T_OUT  3999

typedef unsigned long long ull;

// Scratch: S[b][n][t]  (n = 0..511)
__device__ float g_S[(size_t)NB * 512 * T_IN];          // 65.5 MB
__device__ float g_ct[256 * 256];                        // cos coeffs (E)
__device__ float g_st[256 * 256];                        // sin coeffs (O)

// ---------------------------------------------------------------------------
__global__ void init_tables_kernel() {
    int k = blockIdx.x;
    int n = threadIdx.x;
    float x = (float)(n * k) / 256.0f;
    g_ct[k * 256 + n] = (k == 0) ? 1.0f : 2.0f * cospif(x);
    g_st[k * 256 + n] = 2.0f * sinpif(x);
}

// ---------------------------------------------------------------------------
// Packed dual-FMA: two independent fp32 FMAs per instruction (sm_100+).
__device__ __forceinline__ ull fma2(ull a, ull b, ull c) {
    ull d;
    asm("fma.rn.f32x2 %0, %1, %2, %3;" : "=l"(d) : "l"(a), "l"(b), "l"(c));
    return d;
}
__device__ __forceinline__ float2 u2f(ull v) {
    float2 r;
    r.x = __uint_as_float((unsigned)v);
    r.y = __uint_as_float((unsigned)(v >> 32));
    return r;
}

// ---------------------------------------------------------------------------
// GEMM with f32x2 packed math.
// Block: 256 threads, BN=128 (n), BC=64 (c), BK=16. Micro-tile 8n x 4c, dual
// accumulators (E,O), n-dimension packed in pairs, X operands stored
// DUPLICATED in smem so (x,x) pairs load directly (no pack instructions).
// ---------------------------------------------------------------------------
__global__ __launch_bounds__(256) void gemm_kernel(const float* __restrict__ in) {
    __shared__ __align__(16) float sAc[16][128];
    __shared__ __align__(16) float sAs[16][128];
    __shared__ __align__(16) float sXr2[16][128];  // duplicated pairs (64 c)
    __shared__ __align__(16) float sXi2[16][128];

    const int col0 = blockIdx.x * 64;
    const int n0   = blockIdx.y * 128;
    const int tid  = threadIdx.x;
    const int tc   = tid & 15;
    const int tn   = tid >> 4;
    const int c4   = tc * 4;
    const int n8   = tn * 8;

    // Hoist X load addressing (invariant across k-chunks)
    const float* xbase[4];
    int xkr[4], xc[4];
#pragma unroll
    for (int p = 0; p < 4; p++) {
        int f  = tid + p * 256;
        int kr = f >> 6;              // 0..15
        int c  = f & 63;
        int gc = col0 + c;
        int b  = gc / T_IN;
        int t  = gc - b * T_IN;
        xkr[p] = kr;
        xc[p]  = c;
        xbase[p] = in + (size_t)b * D_IN * T_IN + (size_t)kr * T_IN + t;
    }

    ull accE2[4][4];   // [n-pair][c]
    ull accO2[4][4];
#pragma unroll
    for (int i = 0; i < 4; i++)
#pragma unroll
        for (int j = 0; j < 4; j++) { accE2[i][j] = 0ULL; accO2[i][j] = 0ULL; }

    for (int kk0 = 0; kk0 < 256; kk0 += 16) {
        // A tiles: 16x128, float4 (2 per thread per table)
#pragma unroll
        for (int p = 0; p < 2; p++) {
            int f  = tid + p * 256;
            int kr = f >> 5;
            int nf = (f & 31) << 2;
            *(float4*)&sAc[kr][nf] = *(const float4*)&g_ct[(kk0 + kr) * 256 + n0 + nf];
            *(float4*)&sAs[kr][nf] = *(const float4*)&g_st[(kk0 + kr) * 256 + n0 + nf];
        }
        // X tiles: write duplicated (v,v) pairs
#pragma unroll
        for (int p = 0; p < 4; p++) {
            const float* bp = xbase[p] + (size_t)kk0 * T_IN;
            float vr = bp[0];
            float vi = bp[(size_t)257 * T_IN];
            *(float2*)&sXr2[xkr[p]][xc[p] * 2] = make_float2(vr, vr);
            *(float2*)&sXi2[xkr[p]][xc[p] * 2] = make_float2(vi, vi);
        }
        __syncthreads();

#pragma unroll
        for (int k = 0; k < 16; k++) {
            ulonglong2 a01 = *(const ulonglong2*)&sAc[k][n8];
            ulonglong2 a23 = *(const ulonglong2*)&sAc[k][n8 + 4];
            ulonglong2 b01 = *(const ulonglong2*)&sAs[k][n8];
            ulonglong2 b23 = *(const ulonglong2*)&sAs[k][n8 + 4];
            ulonglong2 r01 = *(const ulonglong2*)&sXr2[k][c4 * 2];
            ulonglong2 r23 = *(const ulonglong2*)&sXr2[k][c4 * 2 + 4];
            ulonglong2 i01 = *(const ulonglong2*)&sXi2[k][c4 * 2];
            ulonglong2 i23 = *(const ulonglong2*)&sXi2[k][c4 * 2 + 4];
            ull ap[4] = {a01.x, a01.y, a23.x, a23.y};
            ull bp[4] = {b01.x, b01.y, b23.x, b23.y};
            ull rp[4] = {r01.x, r01.y, r23.x, r23.y};
            ull ip[4] = {i01.x, i01.y, i23.x, i23.y};
#pragma unroll
            for (int i = 0; i < 4; i++)
#pragma unroll
                for (int j = 0; j < 4; j++) {
                    accE2[i][j] = fma2(ap[i], rp[j], accE2[i][j]);
                    accO2[i][j] = fma2(bp[i], ip[j], accO2[i][j]);
                }
        }
        __syncthreads();
    }

    // Write S rows n (E+O) and 512-n (E-O)
#pragma unroll
    for (int j = 0; j < 4; j++) {
        int gc = col0 + c4 + j;
        int b  = gc / T_IN;
        int t  = gc - b * T_IN;
        size_t baseb = (size_t)b * 512 * T_IN + t;
#pragma unroll
        for (int i = 0; i < 4; i++) {
            float2 E = u2f(accE2[i][j]);
            float2 O = u2f(accO2[i][j]);
            int n = n0 + n8 + 2 * i;
            g_S[baseb + (size_t)n * T_IN] = E.x + O.x;
            if (n > 0)
                g_S[baseb + (size_t)(512 - n) * T_IN] = E.x - O.x;
            g_S[baseb + (size_t)(n + 1) * T_IN] = E.y + O.y;
            g_S[baseb + (size_t)(511 - n) * T_IN] = E.y - O.y;
        }
    }
}

// ---------------------------------------------------------------------------
// Row 256: S[b][256][t] = real[0] + 2*sum_{k=1..255} (-1)^k * real[k]
// ---------------------------------------------------------------------------
__global__ void row256_kernel(const float* __restrict__ in) {
    int gc = blockIdx.x * 256 + threadIdx.x;
    if (gc >= NCOLS) return;
    int b = gc / T_IN;
    int t = gc - b * T_IN;
    const float* base = in + (size_t)b * D_IN * T_IN + t;
    float acc = base[0];
#pragma unroll 8
    for (int k = 1; k < 256; k++) {
        float coef = (k & 1) ? -2.0f : 2.0f;
        acc = fmaf(coef, base[(size_t)k * T_IN], acc);
    }
    g_S[(size_t)b * 512 * T_IN + (size_t)256 * T_IN + t] = acc;
}

// ---------------------------------------------------------------------------
// Epilogue: windowed 4-frame overlap-add + flip + transpose.
// out[b, t, j] = 256 * ( win[1023-j]*S[511-j][t]   + win[767-j]*S[255-j][t-1]
//                      + win[511-j]*S[511-j][t-2] + win[255-j]*S[255-j][t-3] )
// 256 threads: j-lane (128) x t-subtile (2x16). smem 35 KB -> ~6 blocks/SM.
// ---------------------------------------------------------------------------
__global__ __launch_bounds__(256) void epilogue_kernel(const float* __restrict__ win,
                                                       float* __restrict__ out) {
    __shared__ float sS0[128][35];   // rows 255-j family; stride 35: gcd(35,32)=1
    __shared__ float sS1[128][35];   // rows 511-j family

    const int t0 = blockIdx.x * 32;
    const int jh = blockIdx.y;            // 0 or 1
    const int b  = blockIdx.z;
    const int j0 = jh * 128;
    const int part0base = 128 * (1 - jh);        // rows 255-j
    const int part1base = 256 + 128 * (1 - jh);  // rows 511-j
    const int tid = threadIdx.x;

    const float* Sb = g_S + (size_t)b * 512 * T_IN;

    for (int idx = tid; idx < 128 * 35; idx += 256) {
        int rr = idx / 35;
        int tc = idx - rr * 35;
        int ts = t0 - 3 + tc;
        float v0 = 0.0f, v1 = 0.0f;
        if (ts >= 0 && ts < T_IN) {
            v0 = __ldg(&Sb[(size_t)(part0base + rr) * T_IN + ts]);
            v1 = __ldg(&Sb[(size_t)(part1base + rr) * T_IN + ts]);
        }
        sS0[rr][tc] = v0;
        sS1[rr][tc] = v1;
    }
    __syncthreads();

    const int jt = tid & 127;          // j within half
    const int th = tid >> 7;           // 0/1: t sub-tile
    const int j  = j0 + jt;
    const int rr = 127 - jt;
    const float w1 = 256.0f * __ldg(&win[1023 - j]);
    const float w2 = 256.0f * __ldg(&win[767 - j]);
    const float w3 = 256.0f * __ldg(&win[511 - j]);
    const float w4 = 256.0f * __ldg(&win[255 - j]);

    const int dt0 = th * 16;
    float* ob = out + ((size_t)b * T_OUT + t0) * 256 + j;
#pragma unroll
    for (int q = 0; q < 16; q++) {
        int dt = dt0 + q;
        int t = t0 + dt;
        if (t >= T_OUT) break;
        float v = w1 * sS1[rr][dt + 3]
                + w2 * sS0[rr][dt + 2]
                + w3 * sS1[rr][dt + 1]
                + w4 * sS0[rr][dt];
        ob[(size_t)dt * 256] = v;
    }
}

// ---------------------------------------------------------------------------
extern "C" void kernel_launch(void* const* d_in, const int* in_sizes, int n_in,
                              void* d_out, int out_size) {
    const float* in  = (const float*)d_in[0];   // (8, 514, 4000) f32
    const float* win = (const float*)d_in[1];   // (1024,) f32
    float* out = (float*)d_out;                 // (8, 3999*256) f32

    init_tables_kernel<<<256, 256>>>();

    dim3 gG(500, 2);
    gemm_kernel<<<gG, 256>>>(in);

    row256_kernel<<<(NCOLS + 255) / 256, 256>>>(in);

    dim3 gE(125, 2, NB);
    epilogue_kernel<<<gE, 256>>>(win, out);
}

// round 4
// speedup vs baseline: 2.0010x; 2.0010x over previous
#include <cuda_runtime.h>
#include <math.h>

// Problem constants
#define NB     8
#define D_IN   514
#define T_IN   4000
#define NCOLS  (NB * T_IN)     // 32000 columns (b,t)
#define T_OUT  3999

// Scratch: S[b][n][t]  (n = 0..511)
__device__ float g_S[(size_t)NB * 512 * T_IN];          // 65.5 MB
// Parity-split coefficient tables, [k2][n] layout, n = 0..127, k2 = 0..127
__device__ float g_cte[128 * 128];   // (k2==0?1:2) * cos(pi*n*k2/128)        (even k = 2k2)
__device__ float g_cto[128 * 128];   // 2 * cos(pi*n*(2k2+1)/256)             (odd  k = 2k2+1)
__device__ float g_ste[128 * 128];   // 2 * sin(pi*n*k2/128)
__device__ float g_sto[128 * 128];   // 2 * sin(pi*n*(2k2+1)/256)

// ---------------------------------------------------------------------------
__global__ void init_tables_kernel() {
    int k2 = blockIdx.x;    // 0..127
    int n  = threadIdx.x;   // 0..127
    float xe = (float)(n * k2) / 128.0f;            // exact
    float xo = (float)(n * (2 * k2 + 1)) / 256.0f;  // exact
    g_cte[k2 * 128 + n] = (k2 == 0 ? 1.0f : 2.0f) * cospif(xe);
    g_ste[k2 * 128 + n] = 2.0f * sinpif(xe);
    g_cto[k2 * 128 + n] = 2.0f * cospif(xo);
    g_sto[k2 * 128 + n] = 2.0f * sinpif(xo);
}

// ---------------------------------------------------------------------------
// Parity-split GEMM. Block: 256 threads, BN=64 (n), BC=64 (c), BK=16 (k2).
// Per-thread micro-tile 4n x 4c with FOUR accumulator sets (Ee,Eo,Oe,Oo).
// Butterfly epilogue writes rows n, 256-n, 256+n, 512-n.
// ---------------------------------------------------------------------------
__global__ __launch_bounds__(256) void gemm_kernel(const float* __restrict__ in) {
    __shared__ __align__(16) float sCe[16][64];
    __shared__ __align__(16) float sCo[16][64];
    __shared__ __align__(16) float sSe[16][64];
    __shared__ __align__(16) float sSo[16][64];
    __shared__ __align__(16) float sXre[16][64];
    __shared__ __align__(16) float sXro[16][64];
    __shared__ __align__(16) float sXie[16][64];
    __shared__ __align__(16) float sXio[16][64];

    const int col0 = blockIdx.x * 64;
    const int n0   = blockIdx.y * 64;
    const int tid  = threadIdx.x;
    const int tc   = tid & 15;
    const int tn   = tid >> 4;
    const int c4   = tc * 4;
    const int n4   = tn * 4;

    // A-tile load indexing: one float4 per table per thread
    const int akr = tid >> 4;          // 0..15
    const int anf = (tid & 15) << 2;   // 0,4,...,60

    // X-tile load addressing (4 passes of 256 threads), hoisted
    const float* xbase[4];
    int xkr[4], xc[4];
#pragma unroll
    for (int p = 0; p < 4; p++) {
        int f  = tid + p * 256;
        int kr = f >> 6;               // 0..15
        int c  = f & 63;
        int gc = col0 + c;
        int b  = gc / T_IN;
        int t  = gc - b * T_IN;
        xkr[p] = kr;
        xc[p]  = c;
        // even-k row for k2 = kr is row 2*kr
        xbase[p] = in + (size_t)b * D_IN * T_IN + (size_t)(2 * kr) * T_IN + t;
    }

    float aEe[4][4], aEo[4][4], aOe[4][4], aOo[4][4];
#pragma unroll
    for (int i = 0; i < 4; i++)
#pragma unroll
        for (int j = 0; j < 4; j++) {
            aEe[i][j] = 0.0f; aEo[i][j] = 0.0f;
            aOe[i][j] = 0.0f; aOo[i][j] = 0.0f;
        }

    for (int kk0 = 0; kk0 < 128; kk0 += 16) {
        // A tiles: 4 tables x 16x64, one float4 per thread per table
        {
            int off = (kk0 + akr) * 128 + n0 + anf;
            *(float4*)&sCe[akr][anf] = *(const float4*)&g_cte[off];
            *(float4*)&sCo[akr][anf] = *(const float4*)&g_cto[off];
            *(float4*)&sSe[akr][anf] = *(const float4*)&g_ste[off];
            *(float4*)&sSo[akr][anf] = *(const float4*)&g_sto[off];
        }
        // X tiles: rows 2k2 (r_e), 2k2+1 (r_o), 257+2k2 (i_e), 258+2k2 (i_o)
#pragma unroll
        for (int p = 0; p < 4; p++) {
            const float* bp = xbase[p] + (size_t)(2 * kk0) * T_IN;
            sXre[xkr[p]][xc[p]] = bp[0];
            sXro[xkr[p]][xc[p]] = bp[T_IN];
            sXie[xkr[p]][xc[p]] = bp[(size_t)257 * T_IN];
            sXio[xkr[p]][xc[p]] = bp[(size_t)258 * T_IN];
        }
        __syncthreads();

#pragma unroll
        for (int k = 0; k < 16; k++) {
            float4 ce = *(float4*)&sCe[k][n4];
            float4 co = *(float4*)&sCo[k][n4];
            float4 se = *(float4*)&sSe[k][n4];
            float4 so = *(float4*)&sSo[k][n4];
            float4 re = *(float4*)&sXre[k][c4];
            float4 ro = *(float4*)&sXro[k][c4];
            float4 ie = *(float4*)&sXie[k][c4];
            float4 io = *(float4*)&sXio[k][c4];
            float cev[4] = {ce.x, ce.y, ce.z, ce.w};
            float cov[4] = {co.x, co.y, co.z, co.w};
            float sev[4] = {se.x, se.y, se.z, se.w};
            float sov[4] = {so.x, so.y, so.z, so.w};
            float rev[4] = {re.x, re.y, re.z, re.w};
            float rov[4] = {ro.x, ro.y, ro.z, ro.w};
            float iev[4] = {ie.x, ie.y, ie.z, ie.w};
            float iov[4] = {io.x, io.y, io.z, io.w};
#pragma unroll
            for (int i = 0; i < 4; i++)
#pragma unroll
                for (int j = 0; j < 4; j++) {
                    aEe[i][j] = fmaf(cev[i], rev[j], aEe[i][j]);
                    aEo[i][j] = fmaf(cov[i], rov[j], aEo[i][j]);
                    aOe[i][j] = fmaf(sev[i], iev[j], aOe[i][j]);
                    aOo[i][j] = fmaf(sov[i], iov[j], aOo[i][j]);
                }
        }
        __syncthreads();
    }

    // Butterfly + write: rows n, 256-n (always), 256+n, 512-n (n>0)
#pragma unroll
    for (int j = 0; j < 4; j++) {
        int gc = col0 + c4 + j;
        int b  = gc / T_IN;
        int t  = gc - b * T_IN;
        size_t baseb = (size_t)b * 512 * T_IN + t;
#pragma unroll
        for (int i = 0; i < 4; i++) {
            int n = n0 + n4 + i;
            float s0 = aEe[i][j] + aEo[i][j];
            float s1 = aOe[i][j] + aOo[i][j];
            float d0 = aEe[i][j] - aEo[i][j];
            float d1 = aOe[i][j] - aOo[i][j];
            g_S[baseb + (size_t)n * T_IN]         = s0 + s1;
            g_S[baseb + (size_t)(256 - n) * T_IN] = d0 - d1;
            if (n > 0) {
                g_S[baseb + (size_t)(512 - n) * T_IN] = s0 - s1;
                g_S[baseb + (size_t)(256 + n) * T_IN] = d0 + d1;
            }
        }
    }
}

// ---------------------------------------------------------------------------
// Rows 128 and 384:
//   E[128] = r[0] + 2*sum_{k2=1..127} (-1)^k2 * r[2k2]
//   O[128] = 2*sum_{k2=0..127} (-1)^k2 * i[2k2+1]       (i[k] = in[257+k])
//   S[128] = E+O,  S[384] = E-O
// ---------------------------------------------------------------------------
__global__ void row128_kernel(const float* __restrict__ in) {
    int gc = blockIdx.x * 256 + threadIdx.x;
    if (gc >= NCOLS) return;
    int b = gc / T_IN;
    int t = gc - b * T_IN;
    const float* base = in + (size_t)b * D_IN * T_IN + t;
    float E = base[0];
    float O = 0.0f;
#pragma unroll 8
    for (int k2 = 1; k2 < 128; k2++) {
        float ce = (k2 & 1) ? -2.0f : 2.0f;
        E = fmaf(ce, base[(size_t)(2 * k2) * T_IN], E);
    }
#pragma unroll 8
    for (int k2 = 0; k2 < 128; k2++) {
        float co = (k2 & 1) ? -2.0f : 2.0f;
        O = fmaf(co, base[(size_t)(258 + 2 * k2) * T_IN], O);
    }
    size_t baseb = (size_t)b * 512 * T_IN + t;
    g_S[baseb + (size_t)128 * T_IN] = E + O;
    g_S[baseb + (size_t)384 * T_IN] = E - O;
}

// ---------------------------------------------------------------------------
// Epilogue (unchanged from R3 — measured 38.7us):
// out[b, t, j] = 256 * ( win[1023-j]*S[511-j][t]   + win[767-j]*S[255-j][t-1]
//                      + win[511-j]*S[511-j][t-2] + win[255-j]*S[255-j][t-3] )
// ---------------------------------------------------------------------------
__global__ __launch_bounds__(256) void epilogue_kernel(const float* __restrict__ win,
                                                       float* __restrict__ out) {
    __shared__ float sS0[128][35];
    __shared__ float sS1[128][35];

    const int t0 = blockIdx.x * 32;
    const int jh = blockIdx.y;
    const int b  = blockIdx.z;
    const int j0 = jh * 128;
    const int part0base = 128 * (1 - jh);        // rows 255-j
    const int part1base = 256 + 128 * (1 - jh);  // rows 511-j
    const int tid = threadIdx.x;

    const float* Sb = g_S + (size_t)b * 512 * T_IN;

    for (int idx = tid; idx < 128 * 35; idx += 256) {
        int rr = idx / 35;
        int tc = idx - rr * 35;
        int ts = t0 - 3 + tc;
        float v0 = 0.0f, v1 = 0.0f;
        if (ts >= 0 && ts < T_IN) {
            v0 = __ldg(&Sb[(size_t)(part0base + rr) * T_IN + ts]);
            v1 = __ldg(&Sb[(size_t)(part1base + rr) * T_IN + ts]);
        }
        sS0[rr][tc] = v0;
        sS1[rr][tc] = v1;
    }
    __syncthreads();

    const int jt = tid & 127;
    const int th = tid >> 7;
    const int j  = j0 + jt;
    const int rr = 127 - jt;
    const float w1 = 256.0f * __ldg(&win[1023 - j]);
    const float w2 = 256.0f * __ldg(&win[767 - j]);
    const float w3 = 256.0f * __ldg(&win[511 - j]);
    const float w4 = 256.0f * __ldg(&win[255 - j]);

    const int dt0 = th * 16;
    float* ob = out + ((size_t)b * T_OUT + t0) * 256 + j;
#pragma unroll
    for (int q = 0; q < 16; q++) {
        int dt = dt0 + q;
        int t = t0 + dt;
        if (t >= T_OUT) break;
        float v = w1 * sS1[rr][dt + 3]
                + w2 * sS0[rr][dt + 2]
                + w3 * sS1[rr][dt + 1]
                + w4 * sS0[rr][dt];
        ob[(size_t)dt * 256] = v;
    }
}

// ---------------------------------------------------------------------------
extern "C" void kernel_launch(void* const* d_in, const int* in_sizes, int n_in,
                              void* d_out, int out_size) {
    const float* in  = (const float*)d_in[0];   // (8, 514, 4000) f32
    const float* win = (const float*)d_in[1];   // (1024,) f32
    float* out = (float*)d_out;                 // (8, 3999*256) f32

    init_tables_kernel<<<128, 128>>>();

    dim3 gG(500, 2);             // 500 col tiles x 2 n tiles (n = 0..127)
    gemm_kernel<<<gG, 256>>>(in);

    row128_kernel<<<(NCOLS + 255) / 256, 256>>>(in);

    dim3 gE(125, 2, NB);
    epilogue_kernel<<<gE, 256>>>(win, out);
}

// round 5
// speedup vs baseline: 5.9169x; 2.9570x over previous
#include <cuda_runtime.h>
#include <math.h>

#define NB    8
#define D_IN  514
#define T_IN  4000
#define T_OUT 3999

// Scratch: S[b][n][t]  (n = 0..511) — ifft_data
__device__ float  g_S[(size_t)NB * 512 * T_IN];   // 65.5 MB
__device__ float2 g_tw256[256];                    // e^{+2pi i e/256}
__device__ float2 g_tw512[128];                    // e^{+pi i k/256}

// ---------------------------------------------------------------------------
__global__ void init_tables_kernel() {
    int i = threadIdx.x;   // 0..255
    g_tw256[i] = make_float2(cospif(i / 128.0f), sinpif(i / 128.0f));
    if (i < 128)
        g_tw512[i] = make_float2(cospif(i / 256.0f), sinpif(i / 256.0f));
}

__device__ __forceinline__ float2 cmul(float2 a, float2 w) {
    return make_float2(a.x * w.x - a.y * w.y, a.x * w.y + a.y * w.x);
}

// ---------------------------------------------------------------------------
// Inverse real FFT per column via 256-pt complex DFT (e^{+} kernel).
// Block: 16 columns, 256 threads = 16 c-lanes x 16 k-lanes.
// s[2q] = Re z[q], s[2q+1] = Im z[q];  z = DFT256(G), radix-4 DIF in-place,
// output digit-reversed (order irrelevant: rows scattered, c coalesced).
// ---------------------------------------------------------------------------
__global__ __launch_bounds__(256) void fft_kernel(const float* __restrict__ in) {
    __shared__ float2 A[256][17];    // [k][c], pad 17 for bank spread
    __shared__ float2 stw[256];

    const int tid = threadIdx.x;
    const int c   = tid & 15;
    const int lk  = tid >> 4;                 // 0..15
    const int gc0 = blockIdx.x * 16;
    const int b   = gc0 / T_IN;               // 16 | 4000 -> never straddles b
    const int t0  = gc0 - b * T_IN;
    const float* base = in + (size_t)b * D_IN * T_IN + t0;

    stw[tid] = g_tw256[tid];

    // ---- Build G[k] in A (natural order) ----
#pragma unroll
    for (int it = 0; it < 9; it++) {
        int kp = lk + 16 * it;
        if (kp > 128) break;
        if (kp == 0) {
            float r0 = base[c];
            A[0][c] = make_float2(r0, r0);
        } else if (kp == 128) {
            float r = base[(size_t)128 * T_IN + c];
            float m = base[(size_t)385 * T_IN + c];     // 257+128
            A[128][c] = make_float2(2.0f * r, 2.0f * m);
        } else {
            float rk = base[(size_t)kp * T_IN + c];
            float mk = base[(size_t)(257 + kp) * T_IN + c];
            float rp = base[(size_t)(256 - kp) * T_IN + c];
            float mp = base[(size_t)(513 - kp) * T_IN + c];
            float Er = rk + rp, Ei = mp - mk;
            float Dr = rk - rp, Di = -(mk + mp);
            float2 w = g_tw512[kp];
            float Or = Dr * w.x - Di * w.y;
            float Oi = Dr * w.y + Di * w.x;
            A[kp][c]       = make_float2(Er - Oi, Ei + Or);
            A[256 - kp][c] = make_float2(Er + Oi, Or - Ei);
        }
    }
    __syncthreads();

    // ---- 4 radix-4 DIF stages (in-place). m = 64,16,4,1 ; L = 256/N_cur ----
#pragma unroll
    for (int s = 0; s < 4; s++) {
        const int m  = 64 >> (2 * s);
        const int L  = 1 << (2 * s);
        const int lg = 6 - 2 * s;             // log2(m)
#pragma unroll
        for (int it = 0; it < 4; it++) {
            int i4  = lk + 16 * it;           // 0..63
            int i   = i4 & (m - 1);
            int sub = i4 >> lg;
            int p0  = (sub << (lg + 2)) + i;  // sub*4m + i
            float2 x0 = A[p0][c];
            float2 x1 = A[p0 + m][c];
            float2 x2 = A[p0 + 2 * m][c];
            float2 x3 = A[p0 + 3 * m][c];
            float t0r = x0.x + x2.x, t0i = x0.y + x2.y;
            float t1r = x0.x - x2.x, t1i = x0.y - x2.y;
            float t2r = x1.x + x3.x, t2i = x1.y + x3.y;
            float t3r = x1.x - x3.x, t3i = x1.y - x3.y;
            float2 u0 = make_float2(t0r + t2r, t0i + t2i);
            float2 u2 = make_float2(t0r - t2r, t0i - t2i);
            float2 u1 = make_float2(t1r - t3i, t1i + t3r);   // t1 + i*t3
            float2 u3 = make_float2(t1r + t3i, t1i - t3r);   // t1 - i*t3
            int e = i * L;
            A[p0][c]         = u0;
            A[p0 + m][c]     = cmul(u1, stw[e]);
            A[p0 + 2 * m][c] = cmul(u2, stw[2 * e]);
            A[p0 + 3 * m][c] = cmul(u3, stw[3 * e]);
        }
        __syncthreads();
    }

    // ---- Scatter: position p holds z[q], q = digitrev4(p). s[2q], s[2q+1] ----
    float* Sb = g_S + (size_t)b * 512 * T_IN + t0;
#pragma unroll
    for (int it = 0; it < 16; it++) {
        int p = lk + 16 * it;
        int q = ((p & 3) << 6) | (((p >> 2) & 3) << 4) |
                (((p >> 4) & 3) << 2) | (p >> 6);
        float2 z = A[p][c];
        Sb[(size_t)(2 * q) * T_IN + c]     = z.x;
        Sb[(size_t)(2 * q + 1) * T_IN + c] = z.y;
    }
}

// ---------------------------------------------------------------------------
// Epilogue (unchanged — measured 38.6us):
// out[b, t, j] = 256 * ( win[1023-j]*S[511-j][t]   + win[767-j]*S[255-j][t-1]
//                      + win[511-j]*S[511-j][t-2] + win[255-j]*S[255-j][t-3] )
// ---------------------------------------------------------------------------
__global__ __launch_bounds__(256) void epilogue_kernel(const float* __restrict__ win,
                                                       float* __restrict__ out) {
    __shared__ float sS0[128][35];
    __shared__ float sS1[128][35];

    const int t0 = blockIdx.x * 32;
    const int jh = blockIdx.y;
    const int b  = blockIdx.z;
    const int j0 = jh * 128;
    const int part0base = 128 * (1 - jh);        // rows 255-j
    const int part1base = 256 + 128 * (1 - jh);  // rows 511-j
    const int tid = threadIdx.x;

    const float* Sb = g_S + (size_t)b * 512 * T_IN;

    for (int idx = tid; idx < 128 * 35; idx += 256) {
        int rr = idx / 35;
        int tc = idx - rr * 35;
        int ts = t0 - 3 + tc;
        float v0 = 0.0f, v1 = 0.0f;
        if (ts >= 0 && ts < T_IN) {
            v0 = __ldg(&Sb[(size_t)(part0base + rr) * T_IN + ts]);
            v1 = __ldg(&Sb[(size_t)(part1base + rr) * T_IN + ts]);
        }
        sS0[rr][tc] = v0;
        sS1[rr][tc] = v1;
    }
    __syncthreads();

    const int jt = tid & 127;
    const int th = tid >> 7;
    const int j  = j0 + jt;
    const int rr = 127 - jt;
    const float w1 = 256.0f * __ldg(&win[1023 - j]);
    const float w2 = 256.0f * __ldg(&win[767 - j]);
    const float w3 = 256.0f * __ldg(&win[511 - j]);
    const float w4 = 256.0f * __ldg(&win[255 - j]);

    const int dt0 = th * 16;
    float* ob = out + ((size_t)b * T_OUT + t0) * 256 + j;
#pragma unroll
    for (int q = 0; q < 16; q++) {
        int dt = dt0 + q;
        int t = t0 + dt;
        if (t >= T_OUT) break;
        float v = w1 * sS1[rr][dt + 3]
                + w2 * sS0[rr][dt + 2]
                + w3 * sS1[rr][dt + 1]
                + w4 * sS0[rr][dt];
        ob[(size_t)dt * 256] = v;
    }
}

// ---------------------------------------------------------------------------
extern "C" void kernel_launch(void* const* d_in, const int* in_sizes, int n_in,
                              void* d_out, int out_size) {
    const float* in  = (const float*)d_in[0];   // (8, 514, 4000) f32
    const float* win = (const float*)d_in[1];   // (1024,) f32
    float* out = (float*)d_out;                 // (8, 3999*256) f32

    init_tables_kernel<<<1, 256>>>();

    fft_kernel<<<2000, 256>>>(in);              // 16 columns per block

    dim3 gE(125, 2, NB);
    epilogue_kernel<<<gE, 256>>>(win, out);
}